// round 9
// baseline (speedup 1.0000x reference)
#include <cuda_runtime.h>

#define BB 256
#define LL 1024
#define DD 126
#define TT 128
#define NTH 256
#define NEGV -10000.0f
#define NCTA 128
#define LN2 0.6931471805599453

typedef unsigned long long ull;

__device__ int g_perm[BB];

// Rank batches by length (descending, index tie-break). O(n^2) rank, n=256.
__global__ void rank_kernel(const int* __restrict__ x_len) {
    __shared__ int lens[BB];
    int t = threadIdx.x;
    lens[t] = x_len[t];
    __syncthreads();
    int mylen = lens[t];
    int r = 0;
    for (int j = 0; j < BB; ++j) {
        int lj = lens[j];
        if (lj > mylen || (lj == mylen && j < t)) r++;
    }
    g_perm[r] = t;
}

__device__ __forceinline__ ull packf2(float lo, float hi) {
    ull r;
    asm("mov.b64 %0, {%1, %2};" : "=l"(r) : "f"(lo), "f"(hi));
    return r;
}
__device__ __forceinline__ void unpackf2(ull v, float& lo, float& hi) {
    asm("mov.b64 {%0, %1}, %2;" : "=f"(lo), "=f"(hi) : "l"(v));
}
__device__ __forceinline__ ull fma2(ull a, ull b, ull c) {
    ull d;
    asm("fma.rn.f32x2 %0, %1, %2, %3;" : "=l"(d) : "l"(a), "l"(b), "l"(c));
    return d;
}

// 64-wide fp32 half-dot: 16 x LDS.128 front-batched, 4 f32x2 accumulators
// (chains of 8), mov-unpack + FADD tree combine. No CVTs anywhere.
__device__ __forceinline__ float halfdot(const ulonglong2* __restrict__ ep,
                                         const ull* __restrict__ m2) {
    ulonglong2 v[16];
#pragma unroll
    for (int q = 0; q < 16; ++q) v[q] = ep[q];
    ull a0 = 0ULL, a1 = 0ULL, a2 = 0ULL, a3 = 0ULL;
#pragma unroll
    for (int q = 0; q < 16; q += 2) {
        a0 = fma2(m2[2 * q + 0], v[q].x,     a0);
        a1 = fma2(m2[2 * q + 1], v[q].y,     a1);
        a2 = fma2(m2[2 * q + 2], v[q + 1].x, a2);
        a3 = fma2(m2[2 * q + 3], v[q + 1].y, a3);
    }
    float s0, s1, s2, s3, s4, s5, s6, s7;
    unpackf2(a0, s0, s1); unpackf2(a1, s2, s3);
    unpackf2(a2, s4, s5); unpackf2(a3, s6, s7);
    return ((s0 + s1) + (s2 + s3)) + ((s4 + s5) + (s6 + s7));
}

// e-vector layout per buffer: 144 fp32 slots. j<64 -> slot j; j>=64 -> slot j+8
// (32-byte pad so lower/upper LDS.128 hit disjoint banks: 4q.. vs 4q+8..).
__device__ __forceinline__ int eslot(int j) { return j + ((j >> 6) << 3); }

__global__ __launch_bounds__(NTH, 1) void crf_kernel(
    const float* __restrict__ x,
    const float* __restrict__ trans,
    const int*   __restrict__ x_len,
    const int*   __restrict__ tags,
    float*       __restrict__ out)
{
    __shared__ __align__(16) float sh_eA[2][144];
    __shared__ __align__(16) float sh_eB[2][144];
    __shared__ float sh_r[2][2];     // [parity][seq]: power-of-2 normalizer, exact
    __shared__ float sh_red[48];     // 8 warps x {vA, emA, trA, vB, emB, trB}

    int tid  = threadIdx.x;
    int warp = tid >> 5;
    int lane = tid & 31;
    int row  = (warp << 4) | (lane & 15);   // output state owned by this thread-pair
    int half = lane >> 4;                   // 0: j in [0,64), 1: j in [64,128)
    bool act = (half == 0);                 // lower-half lanes finalize & store

    int c = blockIdx.x;
    int bA = g_perm[c];            // long sequence
    int bB = g_perm[255 - c];      // short sequence (sorted desc => lenA >= lenB)
    int lenA = x_len[bA];
    int lenB = x_len[bB];

    if (tid < 4) ((float*)sh_r)[tid] = 1.f;
    if (tid < TT) {
        float v = (tid == DD) ? 1.f : 0.f;
        int s = eslot(tid);
        sh_eA[0][s] = v;
        sh_eB[0][s] = v;
    }

    // exp(T)[row, 64*half + 0..63] -> 32 packed f32x2 (shared by both sequences)
    ull m2[32];
    const float* trow = trans + row * TT + (half << 6);
#pragma unroll
    for (int p = 0; p < 32; ++p)
        m2[p] = packf2(__expf(trow[2 * p]), __expf(trow[2 * p + 1]));
    float eTstop = __expf(trans[127 * TT + row]);

    // Emission + transition scores for both sequences (parallel over l, 256-wide)
    float emA = 0.f, trA = 0.f, emB = 0.f, trB = 0.f;
    {
        const int*   tg = tags + bA * LL;
        const float* xb = x + (size_t)bA * LL * DD;
        for (int l = tid; l < lenA; l += NTH) {
            int t = tg[l];
            emA += xb[(size_t)l * DD + t];
            int prev = (l > 0) ? tg[l - 1] : DD;
            trA += trans[t * TT + prev];
            if (l == lenA - 1) trA += trans[127 * TT + t];
        }
        tg = tags + bB * LL;
        xb = x + (size_t)bB * LL * DD;
        for (int l = tid; l < lenB; l += NTH) {
            int t = tg[l];
            emB += xb[(size_t)l * DD + t];
            int prev = (l > 0) ? tg[l - 1] : DD;
            trB += trans[t * TT + prev];
            if (l == lenB - 1) trB += trans[127 * TT + t];
        }
    }
    __syncthreads();

    bool isTag = act && (row < DD);
    const float* xrA = x + (size_t)bA * LL * DD + row;
    const float* xrB = x + (size_t)bB * LL * DD + row;

    // Emission pipeline (lower-half lanes only), prefetch distance 4:
    // Ec (step l) + raw ring l1..l4 -> >=4 outstanding LDGs, covers DRAM 577.
    float EcA = __expf(isTag ? xrA[0] : NEGV);
    float l1A = (lenA > 1 && isTag) ? xrA[DD] : NEGV;
    float l2A = (lenA > 2 && isTag) ? xrA[2 * DD] : NEGV;
    float l3A = (lenA > 3 && isTag) ? xrA[3 * DD] : NEGV;
    float EcB = __expf(isTag ? xrB[0] : NEGV);
    float l1B = (lenB > 1 && isTag) ? xrB[DD] : NEGV;
    float l2B = (lenB > 2 && isTag) ? xrB[2 * DD] : NEGV;
    float l3B = (lenB > 3 && isTag) ? xrB[3 * DD] : NEGV;
    const float* pA = xrA + 4 * (size_t)DD;
    const float* pB = xrB + 4 * (size_t)DD;

    // C accounting (thread 0 = warp0/lane0, an act lane owning row 0):
    // consume an exponent only when its normalizer is used, never at publish.
    int CiA = 0, CiB = 0;
    int pendA = 0, pendB = 0;
    float lastA = 0.f, lastB = 0.f;
    int buf = 0;
    int l = 0;
    int wslot = eslot(row);

    // ---- fused phase: both sequences active ----
    for (; l < lenB; ++l) {
        float l4A = ((l + 4) < lenA && isTag) ? pA[0] : NEGV;
        float l4B = ((l + 4) < lenB && isTag) ? pB[0] : NEGV;
        pA += DD; pB += DD;
        float rA = sh_r[l & 1][0];
        float rB = sh_r[l & 1][1];
        float fA = EcA * rA;
        float fB = EcB * rB;

        const ulonglong2* epA = (const ulonglong2*)(&sh_eA[buf][half * 72]);
        const ulonglong2* epB = (const ulonglong2*)(&sh_eB[buf][half * 72]);
        float psA = halfdot(epA, m2);
        float psB = halfdot(epB, m2);
        float oA = psA + __shfl_xor_sync(0xffffffffu, psA, 16);
        float oB = psB + __shfl_xor_sync(0xffffffffu, psB, 16);

        float wA = oA * fA;
        float wB = oB * fB;
        if (act) {
            sh_eA[buf ^ 1][wslot] = wA;
            sh_eB[buf ^ 1][wslot] = wB;
            lastA = wA; lastB = wB;
        }
        if (tid == 0) {
            CiA += pendA; CiB += pendB;
            int exA = (int)(__float_as_uint(wA) >> 23) - 127;
            int exB = (int)(__float_as_uint(wB) >> 23) - 127;
            pendA = exA; pendB = exB;
            sh_r[(l + 1) & 1][0] = __uint_as_float((unsigned)(127 - exA) << 23);
            sh_r[(l + 1) & 1][1] = __uint_as_float((unsigned)(127 - exB) << 23);
        }
        EcA = __expf(l1A); l1A = l2A; l2A = l3A; l3A = l4A;
        EcB = __expf(l1B); l1B = l2B; l2B = l3B; l3B = l4B;
        buf ^= 1;
        __syncthreads();
    }

    // ---- tail phase: only the long sequence ----
    for (; l < lenA; ++l) {
        float l4A = ((l + 4) < lenA && isTag) ? pA[0] : NEGV;
        pA += DD;
        float rA = sh_r[l & 1][0];
        float fA = EcA * rA;

        const ulonglong2* epA = (const ulonglong2*)(&sh_eA[buf][half * 72]);
        float psA = halfdot(epA, m2);
        float oA = psA + __shfl_xor_sync(0xffffffffu, psA, 16);

        float wA = oA * fA;
        if (act) {
            sh_eA[buf ^ 1][wslot] = wA;
            lastA = wA;
        }
        if (tid == 0) {
            CiA += pendA;
            int exA = (int)(__float_as_uint(wA) >> 23) - 127;
            pendA = exA;
            sh_r[(l + 1) & 1][0] = __uint_as_float((unsigned)(127 - exA) << 23);
        }
        EcA = __expf(l1A); l1A = l2A; l2A = l3A; l3A = l4A;
        buf ^= 1;
        __syncthreads();
    }

    // ---- partition + output for both sequences ----
    float vA = act ? lastA * eTstop : 0.f;
    float vB = act ? lastB * eTstop : 0.f;
    float e1 = emA, t1 = trA, e2 = emB, t2 = trB;
#pragma unroll
    for (int o = 16; o; o >>= 1) {
        vA += __shfl_xor_sync(0xffffffffu, vA, o);
        e1 += __shfl_xor_sync(0xffffffffu, e1, o);
        t1 += __shfl_xor_sync(0xffffffffu, t1, o);
        vB += __shfl_xor_sync(0xffffffffu, vB, o);
        e2 += __shfl_xor_sync(0xffffffffu, e2, o);
        t2 += __shfl_xor_sync(0xffffffffu, t2, o);
    }
    if (lane == 0) {
        sh_red[warp * 6 + 0] = vA;
        sh_red[warp * 6 + 1] = e1;
        sh_red[warp * 6 + 2] = t1;
        sh_red[warp * 6 + 3] = vB;
        sh_red[warp * 6 + 4] = e2;
        sh_red[warp * 6 + 5] = t2;
    }
    __syncthreads();
    if (tid == 0) {
        float SA = 0.f, EA = 0.f, TA = 0.f, SB = 0.f, EB = 0.f, TB = 0.f;
#pragma unroll
        for (int wq = 0; wq < 8; ++wq) {
            SA += sh_red[wq * 6 + 0];
            EA += sh_red[wq * 6 + 1];
            TA += sh_red[wq * 6 + 2];
            SB += sh_red[wq * 6 + 3];
            EB += sh_red[wq * 6 + 4];
            TB += sh_red[wq * 6 + 5];
        }
        float partA = (float)((double)CiA * LN2) + logf(SA);
        float partB = (float)((double)CiB * LN2) + logf(SB);
        out[bA] = TA + EA - partA;
        out[bB] = TB + EB - partB;
    }
}

extern "C" void kernel_launch(void* const* d_in, const int* in_sizes, int n_in,
                              void* d_out, int out_size) {
    const float* x     = (const float*)d_in[0];
    const float* trans = (const float*)d_in[1];
    // d_in[2] = x_mask (unused; prefix mask derived from x_len)
    const int*   xlen  = (const int*)d_in[3];
    const int*   tags  = (const int*)d_in[4];
    float* out = (float*)d_out;

    rank_kernel<<<1, BB>>>(xlen);
    crf_kernel<<<NCTA, NTH>>>(x, trans, xlen, tags, out);
}

// round 10
// speedup vs baseline: 1.3495x; 1.3495x over previous
#include <cuda_runtime.h>
#include <cuda_bf16.h>

#define BB 256
#define LL 1024
#define DD 126
#define TT 128
#define NTH 256
#define NEGV -10000.0f
#define NCTA 128
#define LN2 0.6931471805599453
#define PUB 224   // publisher thread: warp 7 (arbitrated FIRST), lane 0, row 112

__device__ int g_perm[BB];

// Rank batches by length (descending, index tie-break). O(n^2) rank, n=256.
__global__ void rank_kernel(const int* __restrict__ x_len) {
    __shared__ int lens[BB];
    int t = threadIdx.x;
    lens[t] = x_len[t];
    __syncthreads();
    int mylen = lens[t];
    int r = 0;
    for (int j = 0; j < BB; ++j) {
        int lj = lens[j];
        if (lj > mylen || (lj == mylen && j < t)) r++;
    }
    g_perm[r] = t;
}

__device__ __forceinline__ __nv_bfloat162 asbf2(unsigned u) {
    return *reinterpret_cast<__nv_bfloat162*>(&u);
}
__device__ __forceinline__ unsigned asu32(__nv_bfloat162 v) {
    return *reinterpret_cast<unsigned*>(&v);
}

// 64-wide half-dot: 8 x LDS.128 front-batched, 4 bf16x2 accumulators (chains of 8),
// HADD2 tree -> one bf16x2 partial.
__device__ __forceinline__ __nv_bfloat162 halfdot(const uint4* __restrict__ ep,
                                                  const __nv_bfloat162* __restrict__ m2) {
    uint4 v[8];
#pragma unroll
    for (int q = 0; q < 8; ++q) v[q] = ep[q];
    __nv_bfloat162 zz = __floats2bfloat162_rn(0.f, 0.f);
    __nv_bfloat162 a0 = zz, a1 = zz, a2 = zz, a3 = zz;
#pragma unroll
    for (int q = 0; q < 8; ++q) {
        a0 = __hfma2(m2[4 * q + 0], asbf2(v[q].x), a0);
        a1 = __hfma2(m2[4 * q + 1], asbf2(v[q].y), a1);
        a2 = __hfma2(m2[4 * q + 2], asbf2(v[q].z), a2);
        a3 = __hfma2(m2[4 * q + 3], asbf2(v[q].w), a3);
    }
    return __hadd2(__hadd2(a0, a1), __hadd2(a2, a3));
}

// e-vector layout per buffer: 144 bf16 slots. j<64 -> slot j; j>=64 -> slot j+8
// (16-byte pad between halves so lower/upper LDS.128 hit disjoint banks).
__device__ __forceinline__ int eslot(int j) { return j + ((j >> 6) << 3); }

__global__ __launch_bounds__(NTH, 1) void crf_kernel(
    const float* __restrict__ x,
    const float* __restrict__ trans,
    const int*   __restrict__ x_len,
    const int*   __restrict__ tags,
    float*       __restrict__ out)
{
    __shared__ __align__(16) __nv_bfloat16 sh_eA[2][144];
    __shared__ __align__(16) __nv_bfloat16 sh_eB[2][144];
    __shared__ float sh_r[2][2];     // [parity][seq]: power-of-2 normalizer, exact
    __shared__ float sh_red[48];     // 8 warps x {vA, emA, trA, vB, emB, trB}

    int tid  = threadIdx.x;
    int warp = tid >> 5;
    int lane = tid & 31;
    int row  = (warp << 4) | (lane & 15);   // output state owned by this thread-pair
    int half = lane >> 4;                   // 0: j in [0,64), 1: j in [64,128)
    bool act = (half == 0);                 // lower-half lanes finalize & store
    bool isPub = (tid == PUB);              // warp 7 lane 0: first-arbitrated publisher

    int c = blockIdx.x;
    int bA = g_perm[c];            // long sequence
    int bB = g_perm[255 - c];      // short sequence (sorted desc => lenA >= lenB)
    int lenA = x_len[bA];
    int lenB = x_len[bB];

    if (tid < 4) ((float*)sh_r)[tid] = 1.f;
    if (tid < TT) {
        __nv_bfloat16 v = __float2bfloat16((tid == DD) ? 1.f : 0.f);
        int s = eslot(tid);
        sh_eA[0][s] = v;
        sh_eB[0][s] = v;
    }

    // exp(T)[row, 64*half + 0..63] -> 32 packed bf16x2 (shared by both sequences)
    __nv_bfloat162 m2[32];
    const float* trow = trans + row * TT + (half << 6);
#pragma unroll
    for (int p = 0; p < 32; ++p)
        m2[p] = __floats2bfloat162_rn(__expf(trow[2 * p]), __expf(trow[2 * p + 1]));
    float eTstop = __expf(trans[127 * TT + row]);

    // Emission + transition scores for both sequences (parallel over l, 256-wide)
    float emA = 0.f, trA = 0.f, emB = 0.f, trB = 0.f;
    {
        const int*   tg = tags + bA * LL;
        const float* xb = x + (size_t)bA * LL * DD;
        for (int l = tid; l < lenA; l += NTH) {
            int t = tg[l];
            emA += xb[(size_t)l * DD + t];
            int prev = (l > 0) ? tg[l - 1] : DD;
            trA += trans[t * TT + prev];
            if (l == lenA - 1) trA += trans[127 * TT + t];
        }
        tg = tags + bB * LL;
        xb = x + (size_t)bB * LL * DD;
        for (int l = tid; l < lenB; l += NTH) {
            int t = tg[l];
            emB += xb[(size_t)l * DD + t];
            int prev = (l > 0) ? tg[l - 1] : DD;
            trB += trans[t * TT + prev];
            if (l == lenB - 1) trB += trans[127 * TT + t];
        }
    }
    __syncthreads();

    bool isTag = act && (row < DD);
    const float* xrA = x + (size_t)bA * LL * DD + row;
    const float* xrB = x + (size_t)bB * LL * DD + row;

    // Emission pipeline (lower-half lanes only), prefetch distance 4:
    // Ec (step l) + raw ring l1..l3 + in-flight load -> covers DRAM 577.
    float EcA = __expf(isTag ? xrA[0] : NEGV);
    float l1A = (lenA > 1 && isTag) ? xrA[DD] : NEGV;
    float l2A = (lenA > 2 && isTag) ? xrA[2 * DD] : NEGV;
    float l3A = (lenA > 3 && isTag) ? xrA[3 * DD] : NEGV;
    float EcB = __expf(isTag ? xrB[0] : NEGV);
    float l1B = (lenB > 1 && isTag) ? xrB[DD] : NEGV;
    float l2B = (lenB > 2 && isTag) ? xrB[2 * DD] : NEGV;
    float l3B = (lenB > 3 && isTag) ? xrB[3 * DD] : NEGV;
    const float* pA = xrA + 4 * (size_t)DD;
    const float* pB = xrB + 4 * (size_t)DD;

    // C accounting (publisher thread): consume an exponent only when its
    // normalizer is used (next step), never at publish.
    int CiA = 0, CiB = 0;
    int pendA = 0, pendB = 0;
    float lastA = 0.f, lastB = 0.f;
    int buf = 0;
    int l = 0;
    int wslot = eslot(row);

    // ---- fused phase: both sequences active ----
    for (; l < lenB; ++l) {
        float l4A = ((l + 4) < lenA && isTag) ? pA[0] : NEGV;
        float l4B = ((l + 4) < lenB && isTag) ? pB[0] : NEGV;
        pA += DD; pB += DD;
        float rA = sh_r[l & 1][0];
        float rB = sh_r[l & 1][1];
        float fA = EcA * rA;
        float fB = EcB * rB;

        const uint4* epA = (const uint4*)(&sh_eA[buf][half * 72]);
        const uint4* epB = (const uint4*)(&sh_eB[buf][half * 72]);
        __nv_bfloat162 hA = halfdot(epA, m2);
        __nv_bfloat162 hB = halfdot(epB, m2);
        __nv_bfloat162 tA = __hadd2(hA, asbf2(__shfl_xor_sync(0xffffffffu, asu32(hA), 16)));
        __nv_bfloat162 tB = __hadd2(hB, asbf2(__shfl_xor_sync(0xffffffffu, asu32(hB), 16)));
        float2 cA = __bfloat1622float2(tA);
        float2 cB = __bfloat1622float2(tB);
        float wA = (cA.x + cA.y) * fA;
        float wB = (cB.x + cB.y) * fB;

        if (act) {
            sh_eA[buf ^ 1][wslot] = __float2bfloat16(wA);
            sh_eB[buf ^ 1][wslot] = __float2bfloat16(wB);
            lastA = wA; lastB = wB;
        }
        if (isPub) {
            CiA += pendA; CiB += pendB;
            unsigned ua = __float_as_uint(wA);
            unsigned ub = __float_as_uint(wB);
            sh_r[(l + 1) & 1][0] = __uint_as_float(0x7F000000u - (ua & 0x7F800000u));
            sh_r[(l + 1) & 1][1] = __uint_as_float(0x7F000000u - (ub & 0x7F800000u));
            pendA = (int)(ua >> 23) - 127;
            pendB = (int)(ub >> 23) - 127;
        }
        EcA = __expf(l1A); l1A = l2A; l2A = l3A; l3A = l4A;
        EcB = __expf(l1B); l1B = l2B; l2B = l3B; l3B = l4B;
        buf ^= 1;
        __syncthreads();
    }

    // ---- tail phase: only the long sequence ----
    for (; l < lenA; ++l) {
        float l4A = ((l + 4) < lenA && isTag) ? pA[0] : NEGV;
        pA += DD;
        float rA = sh_r[l & 1][0];
        float fA = EcA * rA;

        const uint4* epA = (const uint4*)(&sh_eA[buf][half * 72]);
        __nv_bfloat162 hA = halfdot(epA, m2);
        __nv_bfloat162 tA = __hadd2(hA, asbf2(__shfl_xor_sync(0xffffffffu, asu32(hA), 16)));
        float2 cA = __bfloat1622float2(tA);
        float wA = (cA.x + cA.y) * fA;

        if (act) {
            sh_eA[buf ^ 1][wslot] = __float2bfloat16(wA);
            lastA = wA;
        }
        if (isPub) {
            CiA += pendA;
            unsigned ua = __float_as_uint(wA);
            sh_r[(l + 1) & 1][0] = __uint_as_float(0x7F000000u - (ua & 0x7F800000u));
            pendA = (int)(ua >> 23) - 127;
        }
        EcA = __expf(l1A); l1A = l2A; l2A = l3A; l3A = l4A;
        buf ^= 1;
        __syncthreads();
    }

    // ---- partition + output for both sequences ----
    float vA = act ? lastA * eTstop : 0.f;
    float vB = act ? lastB * eTstop : 0.f;
    float e1 = emA, t1 = trA, e2 = emB, t2 = trB;
#pragma unroll
    for (int o = 16; o; o >>= 1) {
        vA += __shfl_xor_sync(0xffffffffu, vA, o);
        e1 += __shfl_xor_sync(0xffffffffu, e1, o);
        t1 += __shfl_xor_sync(0xffffffffu, t1, o);
        vB += __shfl_xor_sync(0xffffffffu, vB, o);
        e2 += __shfl_xor_sync(0xffffffffu, e2, o);
        t2 += __shfl_xor_sync(0xffffffffu, t2, o);
    }
    if (lane == 0) {
        sh_red[warp * 6 + 0] = vA;
        sh_red[warp * 6 + 1] = e1;
        sh_red[warp * 6 + 2] = t1;
        sh_red[warp * 6 + 3] = vB;
        sh_red[warp * 6 + 4] = e2;
        sh_red[warp * 6 + 5] = t2;
    }
    __syncthreads();
    if (isPub) {
        float SA = 0.f, EA = 0.f, TA = 0.f, SB = 0.f, EB = 0.f, TB = 0.f;
#pragma unroll
        for (int wq = 0; wq < 8; ++wq) {
            SA += sh_red[wq * 6 + 0];
            EA += sh_red[wq * 6 + 1];
            TA += sh_red[wq * 6 + 2];
            SB += sh_red[wq * 6 + 3];
            EB += sh_red[wq * 6 + 4];
            TB += sh_red[wq * 6 + 5];
        }
        float partA = (float)((double)CiA * LN2) + logf(SA);
        float partB = (float)((double)CiB * LN2) + logf(SB);
        out[bA] = TA + EA - partA;
        out[bB] = TB + EB - partB;
    }
}

extern "C" void kernel_launch(void* const* d_in, const int* in_sizes, int n_in,
                              void* d_out, int out_size) {
    const float* x     = (const float*)d_in[0];
    const float* trans = (const float*)d_in[1];
    // d_in[2] = x_mask (unused; prefix mask derived from x_len)
    const int*   xlen  = (const int*)d_in[3];
    const int*   tags  = (const int*)d_in[4];
    float* out = (float*)d_out;

    rank_kernel<<<1, BB>>>(xlen);
    crf_kernel<<<NCTA, NTH>>>(x, trans, xlen, tags, out);
}

// round 11
// speedup vs baseline: 1.3989x; 1.0366x over previous
#include <cuda_runtime.h>
#include <cuda_bf16.h>

#define BB 256
#define LL 1024
#define DD 126
#define TT 128
#define NTH 256
#define NEGV -10000.0f
#define NCTA 128
#define LN2 0.6931471805599453
#define PUB 224   // publisher thread: warp 7 (arbitrated FIRST), lane 0, row 112

__device__ int g_perm[BB];

// Rank batches by length (descending, index tie-break). O(n^2) rank, n=256.
__global__ void rank_kernel(const int* __restrict__ x_len) {
    __shared__ int lens[BB];
    int t = threadIdx.x;
    lens[t] = x_len[t];
    __syncthreads();
    int mylen = lens[t];
    int r = 0;
    for (int j = 0; j < BB; ++j) {
        int lj = lens[j];
        if (lj > mylen || (lj == mylen && j < t)) r++;
    }
    g_perm[r] = t;
}

__device__ __forceinline__ __nv_bfloat162 asbf2(unsigned u) {
    return *reinterpret_cast<__nv_bfloat162*>(&u);
}
__device__ __forceinline__ unsigned asu32(__nv_bfloat162 v) {
    return *reinterpret_cast<unsigned*>(&v);
}

// 64-wide half-dot: 8 x LDS.128 front-batched, 4 bf16x2 accumulators (chains of 8),
// HADD2 tree -> one bf16x2 partial.
__device__ __forceinline__ __nv_bfloat162 halfdot(const uint4* __restrict__ ep,
                                                  const __nv_bfloat162* __restrict__ m2) {
    uint4 v[8];
#pragma unroll
    for (int q = 0; q < 8; ++q) v[q] = ep[q];
    __nv_bfloat162 zz = __floats2bfloat162_rn(0.f, 0.f);
    __nv_bfloat162 a0 = zz, a1 = zz, a2 = zz, a3 = zz;
#pragma unroll
    for (int q = 0; q < 8; ++q) {
        a0 = __hfma2(m2[4 * q + 0], asbf2(v[q].x), a0);
        a1 = __hfma2(m2[4 * q + 1], asbf2(v[q].y), a1);
        a2 = __hfma2(m2[4 * q + 2], asbf2(v[q].z), a2);
        a3 = __hfma2(m2[4 * q + 3], asbf2(v[q].w), a3);
    }
    return __hadd2(__hadd2(a0, a1), __hadd2(a2, a3));
}

// e-vector layout per buffer: 144 bf16 slots. j<64 -> slot j; j>=64 -> slot j+8
// (16-byte pad between halves so lower/upper LDS.128 hit disjoint banks).
__device__ __forceinline__ int eslot(int j) { return j + ((j >> 6) << 3); }

__global__ __launch_bounds__(NTH, 1) void crf_kernel(
    const float* __restrict__ x,
    const float* __restrict__ trans,
    const int*   __restrict__ x_len,
    const int*   __restrict__ tags,
    float*       __restrict__ out)
{
    __shared__ __align__(16) __nv_bfloat16 sh_eA[2][144];
    __shared__ __align__(16) __nv_bfloat16 sh_eB[2][144];
    __shared__ float sh_r[2][2];     // [parity=buf][seq]: power-of-2 normalizer, exact
    __shared__ float sh_red[48];     // 8 warps x {vA, emA, trA, vB, emB, trB}

    int tid  = threadIdx.x;
    int warp = tid >> 5;
    int lane = tid & 31;
    int row  = (warp << 4) | (lane & 15);   // output state owned by this thread-pair
    int half = lane >> 4;                   // 0: j in [0,64), 1: j in [64,128)
    bool act = (half == 0);                 // lower-half lanes finalize & store
    bool isPub = (tid == PUB);              // warp 7 lane 0: first-arbitrated publisher

    int c = blockIdx.x;
    int bA = g_perm[c];            // long sequence
    int bB = g_perm[255 - c];      // short sequence (sorted desc => lenA >= lenB)
    int lenA = x_len[bA];
    int lenB = x_len[bB];

    if (tid < 4) ((float*)sh_r)[tid] = 1.f;
    if (tid < TT) {
        __nv_bfloat16 v = __float2bfloat16((tid == DD) ? 1.f : 0.f);
        int s = eslot(tid);
        sh_eA[0][s] = v;
        sh_eB[0][s] = v;
    }

    // exp(T)[row, 64*half + 0..63] -> 32 packed bf16x2 (shared by both sequences)
    __nv_bfloat162 m2[32];
    const float* trow = trans + row * TT + (half << 6);
#pragma unroll
    for (int p = 0; p < 32; ++p)
        m2[p] = __floats2bfloat162_rn(__expf(trow[2 * p]), __expf(trow[2 * p + 1]));
    float eTstop = __expf(trans[127 * TT + row]);

    // Emission + transition scores for both sequences (parallel over l, 256-wide)
    float emA = 0.f, trA = 0.f, emB = 0.f, trB = 0.f;
    {
        const int*   tg = tags + bA * LL;
        const float* xb = x + (size_t)bA * LL * DD;
        for (int l = tid; l < lenA; l += NTH) {
            int t = tg[l];
            emA += xb[(size_t)l * DD + t];
            int prev = (l > 0) ? tg[l - 1] : DD;
            trA += trans[t * TT + prev];
            if (l == lenA - 1) trA += trans[127 * TT + t];
        }
        tg = tags + bB * LL;
        xb = x + (size_t)bB * LL * DD;
        for (int l = tid; l < lenB; l += NTH) {
            int t = tg[l];
            emB += xb[(size_t)l * DD + t];
            int prev = (l > 0) ? tg[l - 1] : DD;
            trB += trans[t * TT + prev];
            if (l == lenB - 1) trB += trans[127 * TT + t];
        }
    }
    __syncthreads();

    bool isTag = act && (row < DD);
    const float* xrA = x + (size_t)bA * LL * DD + row;
    const float* xrB = x + (size_t)bB * LL * DD + row;

    // Fused-phase emission pipeline (scalar ring, prefetch distance 4)
    float EcA = __expf(isTag ? xrA[0] : NEGV);
    float l1A = (lenA > 1 && isTag) ? xrA[DD] : NEGV;
    float l2A = (lenA > 2 && isTag) ? xrA[2 * DD] : NEGV;
    float l3A = (lenA > 3 && isTag) ? xrA[3 * DD] : NEGV;
    float EcB = __expf(isTag ? xrB[0] : NEGV);
    float l1B = (lenB > 1 && isTag) ? xrB[DD] : NEGV;
    float l2B = (lenB > 2 && isTag) ? xrB[2 * DD] : NEGV;
    float l3B = (lenB > 3 && isTag) ? xrB[3 * DD] : NEGV;
    const float* pA = xrA + 4 * (size_t)DD;
    const float* pB = xrB + 4 * (size_t)DD;

    // C accounting (publisher): consume an exponent only when its normalizer is
    // used (next step), never at publish.
    int CiA = 0, CiB = 0;
    int pendA = 0, pendB = 0;
    float lastA = 0.f, lastB = 0.f;
    int buf = 0;
    int l = 0;
    int wslot = eslot(row);

    // ---- fused phase: both sequences active ----
    for (; l < lenB; ++l) {
        float l4A = ((l + 4) < lenA && isTag) ? pA[0] : NEGV;
        float l4B = ((l + 4) < lenB && isTag) ? pB[0] : NEGV;
        pA += DD; pB += DD;
        float rA = sh_r[buf][0];
        float rB = sh_r[buf][1];
        float fA = EcA * rA;
        float fB = EcB * rB;

        const uint4* epA = (const uint4*)(&sh_eA[buf][half * 72]);
        const uint4* epB = (const uint4*)(&sh_eB[buf][half * 72]);
        __nv_bfloat162 hA = halfdot(epA, m2);
        __nv_bfloat162 hB = halfdot(epB, m2);
        __nv_bfloat162 tA = __hadd2(hA, asbf2(__shfl_xor_sync(0xffffffffu, asu32(hA), 16)));
        __nv_bfloat162 tB = __hadd2(hB, asbf2(__shfl_xor_sync(0xffffffffu, asu32(hB), 16)));
        float2 cA = __bfloat1622float2(tA);
        float2 cB = __bfloat1622float2(tB);
        float wA = (cA.x + cA.y) * fA;
        float wB = (cB.x + cB.y) * fB;

        if (act) {
            sh_eA[buf ^ 1][wslot] = __float2bfloat16(wA);
            sh_eB[buf ^ 1][wslot] = __float2bfloat16(wB);
            lastA = wA; lastB = wB;
        }
        if (isPub) {
            CiA += pendA; CiB += pendB;
            unsigned ua = __float_as_uint(wA);
            unsigned ub = __float_as_uint(wB);
            sh_r[buf ^ 1][0] = __uint_as_float(0x7F000000u - (ua & 0x7F800000u));
            sh_r[buf ^ 1][1] = __uint_as_float(0x7F000000u - (ub & 0x7F800000u));
            pendA = (int)(ua >> 23) - 127;
            pendB = (int)(ub >> 23) - 127;
        }
        EcA = __expf(l1A); l1A = l2A; l2A = l3A; l3A = l4A;
        EcB = __expf(l1B); l1B = l2B; l2B = l3B; l3B = l4B;
        buf ^= 1;
        __syncthreads();
    }

    // ---- tail phase (long sequence only), chunked by 8 with register-ring E ----
    float Ecur[8], rawP[8], rawN[8];
    if (l < lenA) {
        // Prime: E for steps l..l+7, raw for l+8..l+15 and l+16..l+23 (clamped).
#pragma unroll
        for (int k = 0; k < 8; ++k) {
            int i0 = l + k;       if (i0 > lenA - 1) i0 = lenA - 1;
            int i1 = l + 8 + k;   if (i1 > lenA - 1) i1 = lenA - 1;
            int i2 = l + 16 + k;  if (i2 > lenA - 1) i2 = lenA - 1;
            Ecur[k] = __expf(isTag ? xrA[(size_t)i0 * DD] : NEGV);
            rawP[k] = isTag ? xrA[(size_t)i1 * DD] : NEGV;
            rawN[k] = isTag ? xrA[(size_t)i2 * DD] : NEGV;
        }
    }
    while (lenA - l >= 8) {
#pragma unroll
        for (int k = 0; k < 8; ++k) {
            float rA = sh_r[buf][0];
            float fA = Ecur[k] * rA;

            const uint4* epA = (const uint4*)(&sh_eA[buf][half * 72]);
            __nv_bfloat162 hA = halfdot(epA, m2);
            __nv_bfloat162 tA = __hadd2(hA, asbf2(__shfl_xor_sync(0xffffffffu, asu32(hA), 16)));
            float2 cA = __bfloat1622float2(tA);
            float wA = (cA.x + cA.y) * fA;

            if (act) {
                sh_eA[buf ^ 1][wslot] = __float2bfloat16(wA);
                lastA = wA;
            }
            if (isPub) {
                CiA += pendA;
                unsigned ua = __float_as_uint(wA);
                sh_r[buf ^ 1][0] = __uint_as_float(0x7F000000u - (ua & 0x7F800000u));
                pendA = (int)(ua >> 23) - 127;
            }
            // Rotate ring: convert 8-ahead raw, load 24-ahead (clamped).
            Ecur[k] = __expf(rawP[k]);
            rawP[k] = rawN[k];
            int i2 = l + 24 + k;  if (i2 > lenA - 1) i2 = lenA - 1;
            rawN[k] = isTag ? xrA[(size_t)i2 * DD] : NEGV;
            buf ^= 1;
            __syncthreads();
        }
        l += 8;
    }
    // Remainder (< 8 steps), static-unrolled with uniform guards.
#pragma unroll
    for (int k = 0; k < 8; ++k) {
        if (l + k < lenA) {
            float rA = sh_r[buf][0];
            float fA = Ecur[k] * rA;

            const uint4* epA = (const uint4*)(&sh_eA[buf][half * 72]);
            __nv_bfloat162 hA = halfdot(epA, m2);
            __nv_bfloat162 tA = __hadd2(hA, asbf2(__shfl_xor_sync(0xffffffffu, asu32(hA), 16)));
            float2 cA = __bfloat1622float2(tA);
            float wA = (cA.x + cA.y) * fA;

            if (act) {
                sh_eA[buf ^ 1][wslot] = __float2bfloat16(wA);
                lastA = wA;
            }
            if (isPub) {
                CiA += pendA;
                unsigned ua = __float_as_uint(wA);
                sh_r[buf ^ 1][0] = __uint_as_float(0x7F000000u - (ua & 0x7F800000u));
                pendA = (int)(ua >> 23) - 127;
            }
            buf ^= 1;
            __syncthreads();
        }
    }

    // ---- partition + output for both sequences ----
    float vA = act ? lastA * eTstop : 0.f;
    float vB = act ? lastB * eTstop : 0.f;
    float e1 = emA, t1 = trA, e2 = emB, t2 = trB;
#pragma unroll
    for (int o = 16; o; o >>= 1) {
        vA += __shfl_xor_sync(0xffffffffu, vA, o);
        e1 += __shfl_xor_sync(0xffffffffu, e1, o);
        t1 += __shfl_xor_sync(0xffffffffu, t1, o);
        vB += __shfl_xor_sync(0xffffffffu, vB, o);
        e2 += __shfl_xor_sync(0xffffffffu, e2, o);
        t2 += __shfl_xor_sync(0xffffffffu, t2, o);
    }
    if (lane == 0) {
        sh_red[warp * 6 + 0] = vA;
        sh_red[warp * 6 + 1] = e1;
        sh_red[warp * 6 + 2] = t1;
        sh_red[warp * 6 + 3] = vB;
        sh_red[warp * 6 + 4] = e2;
        sh_red[warp * 6 + 5] = t2;
    }
    __syncthreads();
    if (isPub) {
        float SA = 0.f, EA = 0.f, TA = 0.f, SB = 0.f, EB = 0.f, TB = 0.f;
#pragma unroll
        for (int wq = 0; wq < 8; ++wq) {
            SA += sh_red[wq * 6 + 0];
            EA += sh_red[wq * 6 + 1];
            TA += sh_red[wq * 6 + 2];
            SB += sh_red[wq * 6 + 3];
            EB += sh_red[wq * 6 + 4];
            TB += sh_red[wq * 6 + 5];
        }
        float partA = (float)((double)CiA * LN2) + logf(SA);
        float partB = (float)((double)CiB * LN2) + logf(SB);
        out[bA] = TA + EA - partA;
        out[bB] = TB + EB - partB;
    }
}

extern "C" void kernel_launch(void* const* d_in, const int* in_sizes, int n_in,
                              void* d_out, int out_size) {
    const float* x     = (const float*)d_in[0];
    const float* trans = (const float*)d_in[1];
    // d_in[2] = x_mask (unused; prefix mask derived from x_len)
    const int*   xlen  = (const int*)d_in[3];
    const int*   tags  = (const int*)d_in[4];
    float* out = (float*)d_out;

    rank_kernel<<<1, BB>>>(xlen);
    crf_kernel<<<NCTA, NTH>>>(x, trans, xlen, tags, out);
}